// round 14
// baseline (speedup 1.0000x reference)
#include <cuda_runtime.h>

// Problem constants (from reference setup_inputs)
#define B 8
#define H 100
#define W 100
#define C 512
#define R 300
#define POOL 7
#define ITEMS (B * R * POOL)      // 16800 (b-slowest ordering)
#define GRIDX 1824                // ~12 CTAs/SM on 152 SMs (persistent)

// Persistent grid-stride kernel: each CTA loops over (b, r, py) items.
// Item order is b-slowest, so the set of concurrently-active items spans
// < 1 batch slice (20.5 MB) -> input stays L2-resident, read once from DRAM.
// Per item: 7 px cells, 128 threads * float4 = 512 channels, LDG.128 gather,
// streaming STG.128 output. 40-reg budget lets ptxas overlap the load tail of
// one item with the next item's setup/loads.
__global__ __launch_bounds__(128, 12) void roi_align_kernel(
    const float* __restrict__ x,     // (B, H, W, C)
    const int*   __restrict__ rois,  // (R, 4): x1, y1, w, h
    float*       __restrict__ out)   // (B, R, 7, 7, C)
{
    const int c = threadIdx.x * 4;

    for (int item = blockIdx.x; item < ITEMS; item += GRIDX) {
        // decode item -> (b, r, py); constant divisors -> mul-shift
        const int b   = item / (R * POOL);
        const int rem = item - b * (R * POOL);
        const int r   = rem / POOL;
        const int py  = rem - r * POOL;

        const int4 roi = __ldg(((const int4*)rois) + r);
        const int x1 = roi.x, y1 = roi.y, w = roi.z, h = roi.w;

        // --- y axis coords (replicates JAX fp32 math) ---
        const float sh = (float)h;
        float vy = fmaf((float)py + 0.5f, sh * (1.0f / POOL), -0.5f);
        vy = fminf(fmaxf(vy, 0.0f), sh - 1.0f);
        const float fly = floorf(vy);
        const int   ylo = (int)fly;
        const float fy  = vy - fly;
        const int   yhi = min(ylo + 1, h - 1);

        // x-axis common subexpressions
        const float sw   = (float)w;
        const float stpx = sw * (1.0f / POOL);
        const float clx  = sw - 1.0f;
        const int   xmax = w - 1;

        // 32-bit element offsets (max < 2^31)
        const unsigned rowl_off = (unsigned)(b * (H * W) + (y1 + ylo) * W) * C + c;
        const unsigned rowh_off = (unsigned)(b * (H * W) + (y1 + yhi) * W) * C + c;
        const unsigned out_base = (unsigned)(item * POOL) * C + c;  // (b,r,py)-major

        const float gy = 1.0f - fy;

        #pragma unroll
        for (int px = 0; px < POOL; ++px) {
            // --- x axis coords for this cell (px is a literal) ---
            float vx = fmaf((float)px + 0.5f, stpx, -0.5f);
            vx = fminf(fmaxf(vx, 0.0f), clx);
            float flx = floorf(vx);
            int   xlo = (int)flx;
            float fx  = vx - flx;
            int   xhi = min(xlo + 1, xmax);

            const unsigned ol = (unsigned)(x1 + xlo) * C;
            const unsigned oh = (unsigned)(x1 + xhi) * C;

            // 4 independent LDG.128
            float4 tl = *(const float4*)(x + rowl_off + ol);
            float4 tr = *(const float4*)(x + rowl_off + oh);
            float4 bl = *(const float4*)(x + rowh_off + ol);
            float4 br = *(const float4*)(x + rowh_off + oh);

            // bilinear weights
            const float gx = 1.0f - fx;
            const float w_tl = gx * gy;
            const float w_tr = fx * gy;
            const float w_bl = gx * fy;
            const float w_br = fx * fy;

            float4 o;
            o.x = fmaf(br.x, w_br, fmaf(bl.x, w_bl, fmaf(tr.x, w_tr, tl.x * w_tl)));
            o.y = fmaf(br.y, w_br, fmaf(bl.y, w_bl, fmaf(tr.y, w_tr, tl.y * w_tl)));
            o.z = fmaf(br.z, w_br, fmaf(bl.z, w_bl, fmaf(tr.z, w_tr, tl.z * w_tl)));
            o.w = fmaf(br.w, w_br, fmaf(bl.w, w_bl, fmaf(tr.w, w_tr, tl.w * w_tl)));

            // output is never re-read: streaming store
            __stcs((float4*)(out + out_base + (unsigned)px * C), o);
        }
    }
}

extern "C" void kernel_launch(void* const* d_in, const int* in_sizes, int n_in,
                              void* d_out, int out_size)
{
    const float* x    = (const float*)d_in[0];
    const int*   rois = (const int*)d_in[1];
    float*       out  = (float*)d_out;

    roi_align_kernel<<<GRIDX, 128>>>(x, rois, out);
}